// round 12
// baseline (speedup 1.0000x reference)
#include <cuda_runtime.h>
#include <cuda_fp16.h>
#include <cuda.h>
#include <cstdint>

// ============================================================================
// Problem constants
// ============================================================================
#define B_ROWS 16384
#define D_IN   1024
#define D_OUT  1024
#define KPX    1024          // packed X: x_hi fp16
#define KPW    1024          // packed W: w_hi fp16
#define TILE_M 128
#define TILE_N 128
#define KC     64            // fp16 K elements per pipeline chunk (one 128B SW128 row)
#define CPT    16            // chunks per tile (K = 1024)
#define NTILES 1024          // (16384/128) * (1024/128)
#define GRIDSZ 296           // 2 CTAs x 148 SMs, persistent
#define STAGES 3

#define A_BYTES (TILE_M * 128)              // 16384
#define B_BYTES (TILE_N * 128)              // 16384
#define STAGE_BYTES (A_BYTES + B_BYTES)     // 32768
#define SMEM_BARS (STAGES * STAGE_BYTES)    // 98304
#define SMEM_TOTAL (SMEM_BARS + STAGES * 16)  // 98352 (x2 CTAs/SM = 196.7 KB)

// fp16 scratch (static device memory — no runtime alloc)
__device__ __align__(1024) __half g_Xc[(size_t)B_ROWS * KPX];  // 32 MB
__device__ __align__(1024) __half g_Wc[(size_t)D_OUT * KPW];   //  2 MB (L2-resident)

// ============================================================================
// PTX helpers — sm_90 BASELINE features only (no 'a'-suffix instructions)
// ============================================================================
__device__ __forceinline__ uint32_t smem_to_u32(const void* smem_ptr) {
    uint32_t addr;
    asm("{ .reg .u64 tmp; cvta.to.shared.u64 tmp, %1; cvt.u32.u64 %0, tmp; }"
        : "=r"(addr) : "l"(smem_ptr));
    return addr;
}

#define MBARRIER_INIT(mbar, count) \
    asm volatile("mbarrier.init.shared.b64 [%0], %1;" \
                 :: "r"((uint32_t)(mbar)), "r"((uint32_t)(count)) : "memory")

#define MBARRIER_ARRIVE(mbar) \
    asm volatile("mbarrier.arrive.shared.b64 _, [%0];" \
                 :: "r"((uint32_t)(mbar)) : "memory")

#define MBARRIER_EXPECT_TX(mbar, bytes) \
    asm volatile("mbarrier.arrive.expect_tx.shared.b64 _, [%0], %1;" \
                 :: "r"((uint32_t)(mbar)), "r"((uint32_t)(bytes)) : "memory")

#define MBARRIER_WAIT_PARITY(mbar, phase) do { \
    uint32_t _mbar = (uint32_t)(mbar); \
    uint32_t _par = (uint32_t)(phase); \
    uint32_t _done; \
    asm volatile( \
        "{\n\t.reg .pred p;\n\t" \
        "mbarrier.try_wait.parity.acquire.cta.shared::cta.b64 p, [%1], %2;\n\t" \
        "selp.b32 %0, 1, 0, p;\n\t}" \
        : "=r"(_done) : "r"(_mbar), "r"(_par) : "memory"); \
    if (!_done) { \
        asm volatile( \
            "{\n\t.reg .pred P1;\n\t" \
            "WL_%=:\n\t" \
            "mbarrier.try_wait.parity.acquire.cta.shared::cta.b64 P1, [%0], %1, 0x989680;\n\t" \
            "@P1 bra.uni WD_%=;\n\t" \
            "bra.uni WL_%=;\n\t" \
            "WD_%=:\n\t}" \
            :: "r"(_mbar), "r"(_par) : "memory"); \
    } \
} while (0)

// 2D TMA tile load (sm_90 baseline; NOT the multicast 'a' variant)
__device__ __forceinline__ void tma_load_2d(uint32_t smem_addr,
                                            const CUtensorMap* tmap,
                                            int32_t cx, int32_t cy,
                                            uint32_t mbar) {
    asm volatile(
        "cp.async.bulk.tensor.2d.shared::cta.global.tile.mbarrier::complete_tx::bytes "
        "[%0], [%1, {%2, %3}], [%4];"
        :: "r"(smem_addr), "l"(tmap), "r"(cx), "r"(cy), "r"(mbar)
        : "memory");
}

// ldmatrix x4 (sm_75+)
__device__ __forceinline__ void ldm_x4(uint32_t* d, uint32_t addr) {
    asm volatile("ldmatrix.sync.aligned.m8n8.x4.shared.b16 {%0,%1,%2,%3}, [%4];"
                 : "=r"(d[0]), "=r"(d[1]), "=r"(d[2]), "=r"(d[3]) : "r"(addr));
}

// HMMA m16n8k16 fp16 -> f32 (sm_80+)
__device__ __forceinline__ void mma16816(float* c, const uint32_t* a,
                                         uint32_t b0, uint32_t b1) {
    asm volatile(
        "mma.sync.aligned.m16n8k16.row.col.f32.f16.f16.f32 "
        "{%0,%1,%2,%3}, {%4,%5,%6,%7}, {%8,%9}, {%0,%1,%2,%3};"
        : "+f"(c[0]), "+f"(c[1]), "+f"(c[2]), "+f"(c[3])
        : "r"(a[0]), "r"(a[1]), "r"(a[2]), "r"(a[3]), "r"(b0), "r"(b1));
}

// ============================================================================
// Pack kernels: fp32 -> fp16 (round-to-nearest).
// Dot computes x_hi * w_hi; dropped x_lo*w_hi and x_hi*w_lo are each ~2^-12
// relative (calibrated: R10 one term -> 1.76e-4, R11 both -> 2.49e-4).
// ============================================================================
__global__ void pack_x_kernel(const float* __restrict__ x) {
    int row = blockIdx.x;
    int i = threadIdx.x * 4;
    const float4 v = *reinterpret_cast<const float4*>(x + (size_t)row * D_IN + i);
    __half h[4];
    h[0] = __float2half(v.x); h[1] = __float2half(v.y);
    h[2] = __float2half(v.z); h[3] = __float2half(v.w);
    *reinterpret_cast<uint2*>(g_Xc + (size_t)row * KPX + i) = *reinterpret_cast<uint2*>(h);
}

__global__ void pack_w_kernel(const float* __restrict__ w) {
    int row = blockIdx.x;
    int i = threadIdx.x * 4;
    const float4 v = *reinterpret_cast<const float4*>(w + (size_t)row * D_IN + i);
    __half h[4];
    h[0] = __float2half(v.x); h[1] = __float2half(v.y);
    h[2] = __float2half(v.z); h[3] = __float2half(v.w);
    *reinterpret_cast<uint2*>(g_Wc + (size_t)row * KPW + i) = *reinterpret_cast<uint2*>(h);
}

// ============================================================================
// Epilogue math: out = sigmoid((l + g1 - g2)/T), g = -log(-log u), T = 0.1
// g1 - g2 = log(n2/n1), n = -log(u) > 0.
// neglog_acc: MUFU.LG2 abs error ~2^-22 is catastrophic when -log(u)~1e-7
// (u near 1) -> switch to log1p polynomial there.
// ============================================================================
__device__ __forceinline__ float neglog_acc(float u) {
    float t = u - 1.0f;            // (-1, 0); exact near 1
    float r = -__logf(u);
    if (t > -0.0625f) {
        float p = t * (1.0f + t * (-0.5f + t * (0.33333334f + t * (-0.25f + t * 0.2f))));
        r = -p;                    // -log1p(t)
    }
    return r;
}

__device__ __forceinline__ float gumbel_sig(float l, float uu1, float uu2) {
    float n1 = neglog_acc(uu1);
    float n2 = neglog_acc(uu2);
    float z = (l + __logf(__fdividef(n2, n1))) * 10.0f;
    return __fdividef(1.0f, 1.0f + __expf(-z));
}

// ============================================================================
// Persistent GEMM: C[16384,1024] = Xc·Wc^T (fp16, K=1024)
// 296 persistent CTAs, each streams chunks of ~3-4 tiles through one rolling
// 3-stage TMA ring: the producer prefetches the NEXT tile's chunks before the
// current tile's epilogue runs, hiding epilogue + fill latency.
// CTA 128x128, 8 warps (2M x 4N, warp tile 64x32), HMMA mma.sync,
// fused gumbel epilogue with streaming (ldcs/stcs) epilogue traffic.
// ============================================================================
__device__ __forceinline__ void issue_chunk(uint32_t sb, uint32_t bars,
                                            const CUtensorMap* tA,
                                            const CUtensorMap* tB,
                                            int q, int bid) {
    int s = q % STAGES;
    int tl = q >> 4;                 // local tile ordinal
    int j  = q & (CPT - 1);          // chunk within tile
    int t  = bid + tl * GRIDSZ;      // global tile id
    int n0 = (t & 7) << 7;
    int m0 = (t >> 3) << 7;
    uint32_t full = bars + s * 16;
    MBARRIER_EXPECT_TX(full, STAGE_BYTES);
    uint32_t dstA = sb + s * STAGE_BYTES;
    tma_load_2d(dstA, tA, j * KC, m0, full);
    tma_load_2d(dstA + A_BYTES, tB, j * KC, n0, full);
}

__global__ void __launch_bounds__(256, 2)
gumbel_gemm_kernel(const __grid_constant__ CUtensorMap tmA,
                   const __grid_constant__ CUtensorMap tmB,
                   const float* __restrict__ u1,
                   const float* __restrict__ u2,
                   const float* __restrict__ bias,
                   float* __restrict__ outp) {
    extern __shared__ __align__(1024) char smem[];
    uint32_t sb = smem_to_u32(smem);
    uint32_t bars = sb + SMEM_BARS;     // full[s] @ +s*16, empty[s] @ +s*16+8

    int tid = threadIdx.x;
    int wid = tid >> 5, lane = tid & 31;
    int warp_m = wid & 1;               // 2 warps along M
    int warp_n = wid >> 1;              // 4 warps along N
    int bid = blockIdx.x;

    int ntl = (NTILES - bid + GRIDSZ - 1) / GRIDSZ;   // tiles for this CTA (3 or 4)
    int total = ntl * CPT;

    if (tid == 0) {
#pragma unroll
        for (int s = 0; s < STAGES; ++s) {
            MBARRIER_INIT(bars + s * 16, 1);       // full: producer expect_tx
            MBARRIER_INIT(bars + s * 16 + 8, 8);   // empty: one arrive per warp
        }
        asm volatile("fence.mbarrier_init.release.cluster;" ::: "memory");
    }
    __syncthreads();

    // prologue: fill the ring
    if (tid == 0) {
#pragma unroll
        for (int q = 0; q < STAGES; ++q)
            issue_chunk(sb, bars, &tmA, &tmB, q, bid);
    }

    // per-lane ldmatrix geometry
    int sub = lane >> 3, r8 = lane & 7;
    int a_row = warp_m * 64 + (sub & 1) * 8 + r8;     // + mi*16
    int a_colh = (sub >> 1) * 16;                     // byte offset (0/16)
    int b_row = warp_n * 32 + (sub & 1) * 8 + r8;     // + p*16
    int b_colh = (sub >> 1) * 16;

    float acc[4][4][4];

    int m0 = 0, n0 = 0;
    int cs = 0;            // current stage (0..STAGES-1)
    uint32_t cph = 0;      // current phase parity for stage cs

    for (int q = 0; q < total; ++q) {
        int j = q & (CPT - 1);
        if (j == 0) {
            int t = bid + (q >> 4) * GRIDSZ;
            n0 = (t & 7) << 7;
            m0 = (t >> 3) << 7;
#pragma unroll
            for (int mi = 0; mi < 4; ++mi)
#pragma unroll
                for (int ni = 0; ni < 4; ++ni)
#pragma unroll
                    for (int qq = 0; qq < 4; ++qq) acc[mi][ni][qq] = 0.0f;
        }

        MBARRIER_WAIT_PARITY(bars + cs * 16, cph);

        uint32_t Abase = sb + cs * STAGE_BYTES;
        uint32_t Bbase = Abase + A_BYTES;

#pragma unroll
        for (int ks = 0; ks < 4; ++ks) {
            int kb = ks * 32;   // byte offset of this k16 step
            uint32_t areg[4][4];
#pragma unroll
            for (int mi = 0; mi < 4; ++mi) {
                int row = a_row + mi * 16;
                uint32_t off = (uint32_t)(row * 128 + a_colh + kb);
                ldm_x4(areg[mi], Abase + (off ^ ((uint32_t)(row & 7) << 4)));
            }
            uint32_t breg[2][4];
#pragma unroll
            for (int p = 0; p < 2; ++p) {
                int row = b_row + p * 16;
                uint32_t off = (uint32_t)(row * 128 + b_colh + kb);
                ldm_x4(breg[p], Bbase + (off ^ ((uint32_t)(row & 7) << 4)));
            }
#pragma unroll
            for (int mi = 0; mi < 4; ++mi) {
                mma16816(acc[mi][0], areg[mi], breg[0][0], breg[0][2]);
                mma16816(acc[mi][1], areg[mi], breg[0][1], breg[0][3]);
                mma16816(acc[mi][2], areg[mi], breg[1][0], breg[1][2]);
                mma16816(acc[mi][3], areg[mi], breg[1][1], breg[1][3]);
            }
        }

        __syncwarp();
        if (lane == 0) MBARRIER_ARRIVE(bars + cs * 16 + 8);

        // prefetch chunk q+STAGES (possibly next tile) — BEFORE the epilogue,
        // so next-tile TMA flight overlaps the epilogue below
        if (tid == 0 && q + STAGES < total) {
            MBARRIER_WAIT_PARITY(bars + cs * 16 + 8, cph);
            issue_chunk(sb, bars, &tmA, &tmB, q + STAGES, bid);
        }

        if (j == CPT - 1) {
            // ---- fused epilogue for tile (m0, n0) ----
            int g = lane >> 2, tg = lane & 3;
#pragma unroll
            for (int mi = 0; mi < 4; ++mi) {
#pragma unroll
                for (int ni = 0; ni < 4; ++ni) {
                    int n = n0 + warp_n * 32 + ni * 8 + tg * 2;
                    float2 bv = *reinterpret_cast<const float2*>(bias + n);
#pragma unroll
                    for (int h = 0; h < 2; ++h) {
                        int m = m0 + warp_m * 64 + mi * 16 + g + h * 8;
                        size_t o = (size_t)m * D_OUT + n;
                        float2 a1 = __ldcs(reinterpret_cast<const float2*>(u1 + o));
                        float2 a2 = __ldcs(reinterpret_cast<const float2*>(u2 + o));
                        float l0 = acc[mi][ni][h * 2 + 0] + bv.x;
                        float l1 = acc[mi][ni][h * 2 + 1] + bv.y;
                        float2 ov;
                        ov.x = gumbel_sig(l0, a1.x, a2.x);
                        ov.y = gumbel_sig(l1, a1.y, a2.y);
                        __stcs(reinterpret_cast<float2*>(outp + o), ov);
                    }
                }
            }
        }

        if (++cs == STAGES) { cs = 0; cph ^= 1; }
    }
}

// ============================================================================
// Host launcher (graph-capturable: kernel launches only; tensormap encode is
// a pure host-side driver call fetched through cudart — no -lcuda link dep)
// ============================================================================
typedef CUresult (*PFN_encodeTiled)(
    CUtensorMap*, CUtensorMapDataType, cuuint32_t, void*,
    const cuuint64_t*, const cuuint64_t*, const cuuint32_t*, const cuuint32_t*,
    CUtensorMapInterleave, CUtensorMapSwizzle, CUtensorMapL2promotion,
    CUtensorMapFloatOOBfill);

extern "C" void kernel_launch(void* const* d_in, const int* in_sizes, int n_in,
                              void* d_out, int out_size) {
    const float* x    = (const float*)d_in[0];
    const float* u1   = (const float*)d_in[1];
    const float* u2   = (const float*)d_in[2];
    const float* W    = (const float*)d_in[3];
    const float* bias = (const float*)d_in[4];
    float* out = (float*)d_out;

    void* entry = nullptr;
    cudaDriverEntryPointQueryResult qres;
    cudaGetDriverEntryPoint("cuTensorMapEncodeTiled", &entry,
                            cudaEnableDefault, &qres);
    PFN_encodeTiled enc = (PFN_encodeTiled)entry;

    void* pXc = nullptr; cudaGetSymbolAddress(&pXc, g_Xc);
    void* pWc = nullptr; cudaGetSymbolAddress(&pWc, g_Wc);

    CUtensorMap tmA, tmB;
    {
        cuuint64_t dims[2] = {(cuuint64_t)KPX, (cuuint64_t)B_ROWS};
        cuuint64_t strides[1] = {(cuuint64_t)KPX * 2};
        cuuint32_t box[2] = {KC, TILE_M};          // 64 fp16 = 128B (SW128 max)
        cuuint32_t es[2] = {1, 1};
        enc(&tmA, CU_TENSOR_MAP_DATA_TYPE_FLOAT16, 2, pXc, dims, strides, box,
            es, CU_TENSOR_MAP_INTERLEAVE_NONE, CU_TENSOR_MAP_SWIZZLE_128B,
            CU_TENSOR_MAP_L2_PROMOTION_L2_128B, CU_TENSOR_MAP_FLOAT_OOB_FILL_NONE);
    }
    {
        cuuint64_t dims[2] = {(cuuint64_t)KPW, (cuuint64_t)D_OUT};
        cuuint64_t strides[1] = {(cuuint64_t)KPW * 2};
        cuuint32_t box[2] = {KC, TILE_N};
        cuuint32_t es[2] = {1, 1};
        enc(&tmB, CU_TENSOR_MAP_DATA_TYPE_FLOAT16, 2, pWc, dims, strides, box,
            es, CU_TENSOR_MAP_INTERLEAVE_NONE, CU_TENSOR_MAP_SWIZZLE_128B,
            CU_TENSOR_MAP_L2_PROMOTION_L2_128B, CU_TENSOR_MAP_FLOAT_OOB_FILL_NONE);
    }

    cudaFuncSetAttribute(gumbel_gemm_kernel,
                         cudaFuncAttributeMaxDynamicSharedMemorySize, SMEM_TOTAL);

    pack_x_kernel<<<B_ROWS, 256>>>(x);
    pack_w_kernel<<<D_OUT, 256>>>(W);

    gumbel_gemm_kernel<<<GRIDSZ, 256, SMEM_TOTAL>>>(tmA, tmB, u1, u2, bias, out);
}

// round 13
// speedup vs baseline: 1.9717x; 1.9717x over previous
#include <cuda_runtime.h>
#include <cuda_fp16.h>
#include <cuda.h>
#include <cstdint>

// ============================================================================
// Problem constants
// ============================================================================
#define B_ROWS 16384
#define D_IN   1024
#define D_OUT  1024
#define KPX    1024          // packed X: x_hi fp16
#define KPW    1024          // packed W: w_hi fp16
#define TILE_M 128
#define TILE_N 128
#define KC     64            // fp16 K elements per pipeline chunk (one 128B SW128 row)
#define NCHUNK 16            // K = 1024
#define STAGES 3

#define A_BYTES (TILE_M * 128)              // 16384
#define B_BYTES (TILE_N * 128)              // 16384
#define STAGE_BYTES (A_BYTES + B_BYTES)     // 32768
#define SMEM_BARS (STAGES * STAGE_BYTES)    // 98304
#define SMEM_TOTAL (SMEM_BARS + STAGES * 16)  // 98352 (x2 CTAs/SM = 196.7 KB)

// fp16 scratch (static device memory — no runtime alloc)
__device__ __align__(1024) __half g_Xc[(size_t)B_ROWS * KPX];  // 32 MB
__device__ __align__(1024) __half g_Wc[(size_t)D_OUT * KPW];   //  2 MB (L2-resident)

// ============================================================================
// PTX helpers — sm_90 BASELINE features only (no 'a'-suffix instructions)
// ============================================================================
__device__ __forceinline__ uint32_t smem_to_u32(const void* smem_ptr) {
    uint32_t addr;
    asm("{ .reg .u64 tmp; cvta.to.shared.u64 tmp, %1; cvt.u32.u64 %0, tmp; }"
        : "=r"(addr) : "l"(smem_ptr));
    return addr;
}

#define MBARRIER_INIT(mbar, count) \
    asm volatile("mbarrier.init.shared.b64 [%0], %1;" \
                 :: "r"((uint32_t)(mbar)), "r"((uint32_t)(count)) : "memory")

#define MBARRIER_ARRIVE(mbar) \
    asm volatile("mbarrier.arrive.shared.b64 _, [%0];" \
                 :: "r"((uint32_t)(mbar)) : "memory")

#define MBARRIER_EXPECT_TX(mbar, bytes) \
    asm volatile("mbarrier.arrive.expect_tx.shared.b64 _, [%0], %1;" \
                 :: "r"((uint32_t)(mbar)), "r"((uint32_t)(bytes)) : "memory")

#define MBARRIER_WAIT_PARITY(mbar, phase) do { \
    uint32_t _mbar = (uint32_t)(mbar); \
    uint32_t _par = (uint32_t)(phase); \
    uint32_t _done; \
    asm volatile( \
        "{\n\t.reg .pred p;\n\t" \
        "mbarrier.try_wait.parity.acquire.cta.shared::cta.b64 p, [%1], %2;\n\t" \
        "selp.b32 %0, 1, 0, p;\n\t}" \
        : "=r"(_done) : "r"(_mbar), "r"(_par) : "memory"); \
    if (!_done) { \
        asm volatile( \
            "{\n\t.reg .pred P1;\n\t" \
            "WL_%=:\n\t" \
            "mbarrier.try_wait.parity.acquire.cta.shared::cta.b64 P1, [%0], %1, 0x989680;\n\t" \
            "@P1 bra.uni WD_%=;\n\t" \
            "bra.uni WL_%=;\n\t" \
            "WD_%=:\n\t}" \
            :: "r"(_mbar), "r"(_par) : "memory"); \
    } \
} while (0)

// 2D TMA tile load (sm_90 baseline; NOT the multicast 'a' variant)
__device__ __forceinline__ void tma_load_2d(uint32_t smem_addr,
                                            const CUtensorMap* tmap,
                                            int32_t cx, int32_t cy,
                                            uint32_t mbar) {
    asm volatile(
        "cp.async.bulk.tensor.2d.shared::cta.global.tile.mbarrier::complete_tx::bytes "
        "[%0], [%1, {%2, %3}], [%4];"
        :: "r"(smem_addr), "l"(tmap), "r"(cx), "r"(cy), "r"(mbar)
        : "memory");
}

// ldmatrix x4 (sm_75+)
__device__ __forceinline__ void ldm_x4(uint32_t* d, uint32_t addr) {
    asm volatile("ldmatrix.sync.aligned.m8n8.x4.shared.b16 {%0,%1,%2,%3}, [%4];"
                 : "=r"(d[0]), "=r"(d[1]), "=r"(d[2]), "=r"(d[3]) : "r"(addr));
}

// HMMA m16n8k16 fp16 -> f32 (sm_80+)
__device__ __forceinline__ void mma16816(float* c, const uint32_t* a,
                                         uint32_t b0, uint32_t b1) {
    asm volatile(
        "mma.sync.aligned.m16n8k16.row.col.f32.f16.f16.f32 "
        "{%0,%1,%2,%3}, {%4,%5,%6,%7}, {%8,%9}, {%0,%1,%2,%3};"
        : "+f"(c[0]), "+f"(c[1]), "+f"(c[2]), "+f"(c[3])
        : "r"(a[0]), "r"(a[1]), "r"(a[2]), "r"(a[3]), "r"(b0), "r"(b1));
}

// ============================================================================
// Pack kernels: fp32 -> fp16 (round-to-nearest), 8 elements/thread,
// single 16B store. Dropped x_lo*w_hi and x_hi*w_lo are each ~2^-12 relative
// (calibrated: R10 one term -> 1.76e-4, R11 both -> 2.49e-4).
// ============================================================================
__global__ void pack_x_kernel(const float* __restrict__ x) {
    size_t base = ((size_t)blockIdx.x * 256 + threadIdx.x) * 8;
    float4 v0 = *reinterpret_cast<const float4*>(x + base);
    float4 v1 = *reinterpret_cast<const float4*>(x + base + 4);
    __half h[8];
    h[0] = __float2half(v0.x); h[1] = __float2half(v0.y);
    h[2] = __float2half(v0.z); h[3] = __float2half(v0.w);
    h[4] = __float2half(v1.x); h[5] = __float2half(v1.y);
    h[6] = __float2half(v1.z); h[7] = __float2half(v1.w);
    *reinterpret_cast<uint4*>(g_Xc + base) = *reinterpret_cast<uint4*>(h);
}

__global__ void pack_w_kernel(const float* __restrict__ w) {
    size_t base = ((size_t)blockIdx.x * 256 + threadIdx.x) * 8;
    float4 v0 = *reinterpret_cast<const float4*>(w + base);
    float4 v1 = *reinterpret_cast<const float4*>(w + base + 4);
    __half h[8];
    h[0] = __float2half(v0.x); h[1] = __float2half(v0.y);
    h[2] = __float2half(v0.z); h[3] = __float2half(v0.w);
    h[4] = __float2half(v1.x); h[5] = __float2half(v1.y);
    h[6] = __float2half(v1.z); h[7] = __float2half(v1.w);
    *reinterpret_cast<uint4*>(g_Wc + base) = *reinterpret_cast<uint4*>(h);
}

// ============================================================================
// Epilogue math: out = sigmoid((l + g1 - g2)/T), g = -log(-log u), T = 0.1
//   => out = 1 / (1 + exp(-10 l) * (n1/n2)^10),  n = -log(u) > 0
// The ^10 is 4 multiplies (replaces a MUFU log + mul).
// Overflow-safe: r^10=inf -> out=0 (exp(-10l) >= 3e-7, no 0*inf NaN);
// r^10 underflow->0 -> out=1. Both are the correct limits.
// neglog_acc: MUFU.LG2 abs error ~2^-22 is catastrophic when -log(u)~1e-7
// (u near 1) -> switch to log1p polynomial there.
// ============================================================================
__device__ __forceinline__ float neglog_acc(float u) {
    float t = u - 1.0f;            // (-1, 0); exact near 1
    float r = -__logf(u);
    if (t > -0.0625f) {
        float p = t * (1.0f + t * (-0.5f + t * (0.33333334f + t * (-0.25f + t * 0.2f))));
        r = -p;                    // -log1p(t)
    }
    return r;
}

__device__ __forceinline__ float gumbel_sig(float l, float uu1, float uu2) {
    float n1 = neglog_acc(uu1);
    float n2 = neglog_acc(uu2);
    float r  = __fdividef(n1, n2);
    float r2 = r * r;
    float r4 = r2 * r2;
    float r10 = r4 * r4 * r2;
    float e = __expf(-10.0f * l);
    return __fdividef(1.0f, 1.0f + e * r10);
}

// ============================================================================
// GEMM: C[16384,1024] = Xc·Wc^T (fp16, K=1024)
// CTA 128x128, 8 warps (2M x 4N, warp tile 64x32), KC=64,
// 3-stage TMA pipeline, 2 CTAs/SM, HMMA mma.sync, fused gumbel epilogue
// (epilogue strictly AFTER the mainloop — R12 showed inlining it into the
// chunk loop doubles runtime, attributed to register spills / I$ bloat).
// ============================================================================
__device__ __forceinline__ void issue_chunk(uint32_t sb, uint32_t bars,
                                            const CUtensorMap* tA,
                                            const CUtensorMap* tB,
                                            int j, int s, int m0, int n0) {
    uint32_t full = bars + s * 16;
    MBARRIER_EXPECT_TX(full, STAGE_BYTES);
    uint32_t dstA = sb + s * STAGE_BYTES;
    tma_load_2d(dstA, tA, j * KC, m0, full);
    tma_load_2d(dstA + A_BYTES, tB, j * KC, n0, full);
}

__global__ void __launch_bounds__(256, 2)
gumbel_gemm_kernel(const __grid_constant__ CUtensorMap tmA,
                   const __grid_constant__ CUtensorMap tmB,
                   const float* __restrict__ u1,
                   const float* __restrict__ u2,
                   const float* __restrict__ bias,
                   float* __restrict__ outp) {
    extern __shared__ __align__(1024) char smem[];
    uint32_t sb = smem_to_u32(smem);
    uint32_t bars = sb + SMEM_BARS;     // full[s] @ +s*16, empty[s] @ +s*16+8

    int tid = threadIdx.x;
    int wid = tid >> 5, lane = tid & 31;
    int warp_m = wid & 1;               // 2 warps along M
    int warp_n = wid >> 1;              // 4 warps along N
    int m0 = blockIdx.y * TILE_M;
    int n0 = blockIdx.x * TILE_N;

    if (tid == 0) {
#pragma unroll
        for (int s = 0; s < STAGES; ++s) {
            MBARRIER_INIT(bars + s * 16, 1);       // full: producer expect_tx
            MBARRIER_INIT(bars + s * 16 + 8, 8);   // empty: one arrive per warp
        }
        asm volatile("fence.mbarrier_init.release.cluster;" ::: "memory");
    }
    __syncthreads();

    // prologue: fill all stages
    if (tid == 0) {
#pragma unroll
        for (int j = 0; j < STAGES; ++j)
            issue_chunk(sb, bars, &tmA, &tmB, j, j, m0, n0);
    }

    // per-lane ldmatrix geometry
    int sub = lane >> 3, r8 = lane & 7;
    int a_row = warp_m * 64 + (sub & 1) * 8 + r8;     // + mi*16
    int a_colh = (sub >> 1) * 16;                     // byte offset (0/16)
    int b_row = warp_n * 32 + (sub & 1) * 8 + r8;     // + p*16
    int b_colh = (sub >> 1) * 16;

    float acc[4][4][4];
#pragma unroll
    for (int mi = 0; mi < 4; ++mi)
#pragma unroll
        for (int ni = 0; ni < 4; ++ni)
#pragma unroll
            for (int q = 0; q < 4; ++q) acc[mi][ni][q] = 0.0f;

    int cs = 0;            // current stage (0..STAGES-1)
    uint32_t cph = 0;      // current phase parity for stage cs
    for (int i = 0; i < NCHUNK; ++i) {
        MBARRIER_WAIT_PARITY(bars + cs * 16, cph);

        uint32_t Abase = sb + cs * STAGE_BYTES;
        uint32_t Bbase = Abase + A_BYTES;

#pragma unroll
        for (int ks = 0; ks < 4; ++ks) {
            int kb = ks * 32;   // byte offset of this k16 step
            uint32_t areg[4][4];
#pragma unroll
            for (int mi = 0; mi < 4; ++mi) {
                int row = a_row + mi * 16;
                uint32_t off = (uint32_t)(row * 128 + a_colh + kb);
                ldm_x4(areg[mi], Abase + (off ^ ((uint32_t)(row & 7) << 4)));
            }
            uint32_t breg[2][4];
#pragma unroll
            for (int p = 0; p < 2; ++p) {
                int row = b_row + p * 16;
                uint32_t off = (uint32_t)(row * 128 + b_colh + kb);
                ldm_x4(breg[p], Bbase + (off ^ ((uint32_t)(row & 7) << 4)));
            }
#pragma unroll
            for (int mi = 0; mi < 4; ++mi) {
                mma16816(acc[mi][0], areg[mi], breg[0][0], breg[0][2]);
                mma16816(acc[mi][1], areg[mi], breg[0][1], breg[0][3]);
                mma16816(acc[mi][2], areg[mi], breg[1][0], breg[1][2]);
                mma16816(acc[mi][3], areg[mi], breg[1][1], breg[1][3]);
            }
        }

        __syncwarp();
        if (lane == 0) MBARRIER_ARRIVE(bars + cs * 16 + 8);

        // chunk i+STAGES reuses stage cs; empty[cs] completes parity epoch cph
        if (tid == 0 && i + STAGES < NCHUNK) {
            MBARRIER_WAIT_PARITY(bars + cs * 16 + 8, cph);
            issue_chunk(sb, bars, &tmA, &tmB, i + STAGES, cs, m0, n0);
        }

        if (++cs == STAGES) { cs = 0; cph ^= 1; }
    }

    // ---- fused epilogue (register accumulators -> gumbel sigmoid -> gmem) ----
    int g = lane >> 2, tg = lane & 3;
#pragma unroll
    for (int mi = 0; mi < 4; ++mi) {
#pragma unroll
        for (int ni = 0; ni < 4; ++ni) {
            int n = n0 + warp_n * 32 + ni * 8 + tg * 2;
            float2 bv = *reinterpret_cast<const float2*>(bias + n);
#pragma unroll
            for (int h = 0; h < 2; ++h) {
                int m = m0 + warp_m * 64 + mi * 16 + g + h * 8;
                size_t o = (size_t)m * D_OUT + n;
                float2 a1 = *reinterpret_cast<const float2*>(u1 + o);
                float2 a2 = *reinterpret_cast<const float2*>(u2 + o);
                float l0 = acc[mi][ni][h * 2 + 0] + bv.x;
                float l1 = acc[mi][ni][h * 2 + 1] + bv.y;
                float2 ov;
                ov.x = gumbel_sig(l0, a1.x, a2.x);
                ov.y = gumbel_sig(l1, a1.y, a2.y);
                *reinterpret_cast<float2*>(outp + o) = ov;
            }
        }
    }
}

// ============================================================================
// Host launcher (graph-capturable: kernel launches only; tensormap encode is
// a pure host-side driver call fetched through cudart — no -lcuda link dep)
// ============================================================================
typedef CUresult (*PFN_encodeTiled)(
    CUtensorMap*, CUtensorMapDataType, cuuint32_t, void*,
    const cuuint64_t*, const cuuint64_t*, const cuuint32_t*, const cuuint32_t*,
    CUtensorMapInterleave, CUtensorMapSwizzle, CUtensorMapL2promotion,
    CUtensorMapFloatOOBfill);

extern "C" void kernel_launch(void* const* d_in, const int* in_sizes, int n_in,
                              void* d_out, int out_size) {
    const float* x    = (const float*)d_in[0];
    const float* u1   = (const float*)d_in[1];
    const float* u2   = (const float*)d_in[2];
    const float* W    = (const float*)d_in[3];
    const float* bias = (const float*)d_in[4];
    float* out = (float*)d_out;

    void* entry = nullptr;
    cudaDriverEntryPointQueryResult qres;
    cudaGetDriverEntryPoint("cuTensorMapEncodeTiled", &entry,
                            cudaEnableDefault, &qres);
    PFN_encodeTiled enc = (PFN_encodeTiled)entry;

    void* pXc = nullptr; cudaGetSymbolAddress(&pXc, g_Xc);
    void* pWc = nullptr; cudaGetSymbolAddress(&pWc, g_Wc);

    CUtensorMap tmA, tmB;
    {
        cuuint64_t dims[2] = {(cuuint64_t)KPX, (cuuint64_t)B_ROWS};
        cuuint64_t strides[1] = {(cuuint64_t)KPX * 2};
        cuuint32_t box[2] = {KC, TILE_M};          // 64 fp16 = 128B (SW128 max)
        cuuint32_t es[2] = {1, 1};
        enc(&tmA, CU_TENSOR_MAP_DATA_TYPE_FLOAT16, 2, pXc, dims, strides, box,
            es, CU_TENSOR_MAP_INTERLEAVE_NONE, CU_TENSOR_MAP_SWIZZLE_128B,
            CU_TENSOR_MAP_L2_PROMOTION_L2_128B, CU_TENSOR_MAP_FLOAT_OOB_FILL_NONE);
    }
    {
        cuuint64_t dims[2] = {(cuuint64_t)KPW, (cuuint64_t)D_OUT};
        cuuint64_t strides[1] = {(cuuint64_t)KPW * 2};
        cuuint32_t box[2] = {KC, TILE_N};
        cuuint32_t es[2] = {1, 1};
        enc(&tmB, CU_TENSOR_MAP_DATA_TYPE_FLOAT16, 2, pWc, dims, strides, box,
            es, CU_TENSOR_MAP_INTERLEAVE_NONE, CU_TENSOR_MAP_SWIZZLE_128B,
            CU_TENSOR_MAP_L2_PROMOTION_L2_128B, CU_TENSOR_MAP_FLOAT_OOB_FILL_NONE);
    }

    cudaFuncSetAttribute(gumbel_gemm_kernel,
                         cudaFuncAttributeMaxDynamicSharedMemorySize, SMEM_TOTAL);

    pack_x_kernel<<<B_ROWS * D_IN / (256 * 8), 256>>>(x);   // 8192 blocks
    pack_w_kernel<<<D_OUT * D_IN / (256 * 8), 256>>>(W);    //  512 blocks

    dim3 grid(D_OUT / TILE_N, B_ROWS / TILE_M);   // (8, 128)
    gumbel_gemm_kernel<<<grid, 256, SMEM_TOTAL>>>(tmA, tmB, u1, u2, bias, out);
}